// round 12
// baseline (speedup 1.0000x reference)
#include <cuda_runtime.h>
#include <cuda_fp16.h>
#include <cstdint>

// Problem dims
#define IN_F   4096
#define OUT_F  11008
#define MROWS  2048
#define NUMEL  (IN_F * OUT_F)        // 45,088,768
#define PACKED_N (NUMEL / 2)         // 22,544,384

// GEMM tiling: 128x128 CTA tile, 4 warps (2x2), warp tile 64x64, 2 CTAs/SM
#define BM 128
#define BN 128
#define BK 64
#define KCHUNKS (IN_F / BK)          // 64
#define NST 3
#define A_BYTES (BM * 128)           // 16384
#define B_BYTES (BN * 128)           // 16384
#define STAGE_BYTES (A_BYTES + B_BYTES)   // 32768
#define SMEM_BYTES (NST * STAGE_BYTES + 1024)  // 99328 (x2 CTAs = 198656)

#define NTILE_X (OUT_F / BN)         // 86
#define NTILES  (NTILE_X * (MROWS / BM))  // 1376
#define GRID_PERSIST 296             // 2 CTAs x 148 SMs

// prep kernel split
#define CVT_BLOCKS ((MROWS * IN_F / 4) / 256)   // 8192
#define DEQ_BLOCKS ((PACKED_N / 4) / 256)       // 22016

// Scratch (device globals; no allocation allowed)
__device__ __half g_W[NUMEL];          // dequantized W, row-major [OUT_F][IN_F]
__device__ __half g_X[MROWS * IN_F];   // fp16 x
__device__ unsigned int g_ticket;      // persistent-CTA work counter

__constant__ float c_nf4[16] = {
    -1.0f, -0.6961928009986877f, -0.5250730514526367f, -0.39491748809814453f,
    -0.28444138169288635f, -0.18477343022823334f, -0.09105003625154495f, 0.0f,
    0.07958029955625534f, 0.16093020141124725f, 0.24611230194568634f,
    0.33791524171829224f, 0.44070982933044434f, 0.5626170039176941f,
    0.7229568362236023f, 1.0f};

// ---------------------------------------------------------------------------
// fused prep: blocks [0, CVT_BLOCKS) convert x fp32->fp16,
//             blocks [CVT_BLOCKS, ...) dequant NF4 -> fp16 W via
//             32x-replicated conflict-free smem LUT. Block 0 also resets the
//             gemm ticket counter (prep precedes gemm in-stream, so the reset
//             is ordered before any gemm CTA runs — graph-replay safe).
// ---------------------------------------------------------------------------
__global__ void prep_kernel(const float* __restrict__ x,
                            const int* __restrict__ packed,
                            const float* __restrict__ absmax) {
    __shared__ float lut[16 * 32];
    const int b = blockIdx.x;
    const int tid = threadIdx.x;
    if (b < CVT_BLOCKS) {
        if (b == 0 && tid == 0) g_ticket = 0u;
        int i = b * 256 + tid;                            // handles 4 floats
        float4 v = reinterpret_cast<const float4*>(x)[i];
        __half2* o = reinterpret_cast<__half2*>(g_X);
        o[2 * i]     = __floats2half2_rn(v.x, v.y);
        o[2 * i + 1] = __floats2half2_rn(v.z, v.w);
    } else {
        lut[tid]       = c_nf4[tid >> 5];                 // uniform index
        lut[tid + 256] = c_nf4[(tid + 256) >> 5];
        __syncthreads();
        const int lane = tid & 31;
        int i = (b - CVT_BLOCKS) * 256 + tid;             // packed[4i..4i+3]
        int4 pk = reinterpret_cast<const int4*>(packed)[i];
        float s = absmax[i >> 3];                          // (4i)/32 == i/8
        int v[4] = {pk.x, pk.y, pk.z, pk.w};
        __half h[8];
#pragma unroll
        for (int j = 0; j < 4; j++) {
            float whi = lut[((v[j] >> 4) & 0xF) * 32 + lane];
            float wlo = lut[(v[j] & 0xF) * 32 + lane];
            h[2 * j]     = __float2half_rn(whi * s);
            h[2 * j + 1] = __float2half_rn(wlo * s);
        }
        reinterpret_cast<uint4*>(g_W)[i] = *reinterpret_cast<uint4*>(h);
    }
}

// ---------------------------------------------------------------------------
// PTX helpers
// ---------------------------------------------------------------------------
__device__ __forceinline__ uint32_t smem_u32(const void* p) {
    uint32_t a;
    asm("{ .reg .u64 t; cvta.to.shared.u64 t, %1; cvt.u32.u64 %0, t; }"
        : "=r"(a) : "l"(p));
    return a;
}

__device__ __forceinline__ void cp16(uint32_t saddr, const void* gaddr) {
    asm volatile("cp.async.cg.shared.global [%0], [%1], 16;"
                 :: "r"(saddr), "l"(gaddr));
}

__device__ __forceinline__ void ldm_x4(uint32_t* r, uint32_t addr) {
    asm volatile("ldmatrix.sync.aligned.m8n8.x4.shared.b16 {%0,%1,%2,%3}, [%4];"
                 : "=r"(r[0]), "=r"(r[1]), "=r"(r[2]), "=r"(r[3]) : "r"(addr));
}

__device__ __forceinline__ void mma16816(float* c, const uint32_t* a,
                                         uint32_t b0, uint32_t b1) {
    asm volatile(
        "mma.sync.aligned.m16n8k16.row.col.f32.f16.f16.f32 "
        "{%0,%1,%2,%3}, {%4,%5,%6,%7}, {%8,%9}, {%0,%1,%2,%3};"
        : "+f"(c[0]), "+f"(c[1]), "+f"(c[2]), "+f"(c[3])
        : "r"(a[0]), "r"(a[1]), "r"(a[2]), "r"(a[3]), "r"(b0), "r"(b1));
}

// ---------------------------------------------------------------------------
// GEMM (persistent CTAs): grid of 296 CTAs pulls 128x128 tiles off a global
// atomic ticket until all 1376 are done — removes the 5-wave quantization
// tail (~7% of gemm) of the static grid. Per-warp structure is the round-11
// winner: 4 warps (2x2), warp tile 64x64, fp32 acc, double-buffered ldmatrix
// fragments, 3-stage cp.async ring (distance 2), one __syncthreads/chunk.
// NEW: xor-folded ldsm addressing — smem base aligned to 1024 so bits [5:6]
// of (stage + warp/mi/lane offsets) are 0, making
// (base + ks*32) ^ xorv == base ^ (xorv ^ ks*32); saves one IADD per LDSM.
// ---------------------------------------------------------------------------
__global__ void __launch_bounds__(128, 2)
gemm_kernel(const float* __restrict__ bias, float* __restrict__ out) {
    extern __shared__ char smem_raw[];
    const uint32_t sb = (smem_u32(smem_raw) + 1023u) & ~1023u;
    __shared__ unsigned int s_t;
    const int tid = threadIdx.x;
    const int wid = tid >> 5;
    const int lane = tid & 31;
    const int warp_m = wid >> 1;          // 0..1
    const int warp_n = wid & 1;           // 0..1

    // per-thread ldmatrix lane addressing (SW128; validated round 2)
    const int grp = lane >> 3, lr = lane & 7;
    const uint32_t xorv = (uint32_t)(lr << 4);
    uint32_t xk[4];
#pragma unroll
    for (int ks = 0; ks < 4; ks++) xk[ks] = xorv ^ (uint32_t)(ks << 5);
    const uint32_t laneoff =
        (uint32_t)((((grp & 1) << 3) + lr) << 7) + (uint32_t)((grp >> 1) << 4);
    const uint32_t aoff0 = (uint32_t)((warp_m * 64) << 7) + laneoff;
    const uint32_t boff0 = (uint32_t)((warp_n * 64) << 7) + laneoff;

    // cp.async issue constants (per-thread): 8 units x (A,B)
    uint32_t sw_i[8];
    int r_i[8], sg_i[8];
#pragma unroll
    for (int i = 0; i < 8; i++) {
        int u = tid + (i << 7);
        r_i[i] = u >> 3;
        sg_i[i] = (u & 7) * 8;
        uint32_t bo = (uint32_t)((r_i[i] << 7) + ((u & 7) << 4));
        sw_i[i] = bo ^ ((bo >> 3) & 0x70);
    }

    const int g = lane >> 2, q = lane & 3;   // epilogue lane decomposition

    while (true) {
        if (tid == 0) s_t = atomicAdd(&g_ticket, 1u);
        __syncthreads();                 // broadcast t; also fences smem reuse
        const unsigned int t = s_t;
        if (t >= NTILES) break;

        const int row0 = (int)(t / NTILE_X) * BM;
        const int col0 = (int)(t % NTILE_X) * BN;
        const __half* Ab = g_X + (size_t)row0 * IN_F;
        const __half* Bb = g_W + (size_t)col0 * IN_F;

        auto issue = [&](int c, int s) {
            const int kc = c * BK;
            const uint32_t base = sb + s * STAGE_BYTES;
#pragma unroll
            for (int i = 0; i < 8; i++) {
                cp16(base + sw_i[i], Ab + (size_t)r_i[i] * IN_F + kc + sg_i[i]);
                cp16(base + A_BYTES + sw_i[i],
                     Bb + (size_t)r_i[i] * IN_F + kc + sg_i[i]);
            }
        };

        float C[4][8][4];
#pragma unroll
        for (int a = 0; a < 4; a++)
#pragma unroll
            for (int b = 0; b < 8; b++)
#pragma unroll
                for (int d = 0; d < 4; d++) C[a][b][d] = 0.0f;

        uint32_t af[2][4][4], bf[2][4][4];

        // prologue: 2 chunks in flight
        issue(0, 0);
        asm volatile("cp.async.commit_group;" ::: "memory");
        issue(1, 1);
        asm volatile("cp.async.commit_group;" ::: "memory");

        int s_cur = 0, s_pre = 2;
#pragma unroll 1
        for (int c = 0; c < KCHUNKS; c++) {
            asm volatile("cp.async.wait_group 1;" ::: "memory");
            __syncthreads();   // chunk c landed; all warps past iter c-1 LDSM

            const uint32_t sa = sb + s_cur * STAGE_BYTES;
            const uint32_t sB = sa + A_BYTES;
            // folded ldsm bases (bits [5:6] provably 0 -> xor-composable)
            uint32_t abase[4], bbase[4];
#pragma unroll
            for (int mi = 0; mi < 4; mi++) {
                abase[mi] = sa + aoff0 + (uint32_t)(mi << 11);
                bbase[mi] = sB + boff0 + (uint32_t)(mi << 11);
            }
            auto load_frags = [&](int ks, int buf) {
#pragma unroll
                for (int mi = 0; mi < 4; mi++)
                    ldm_x4(af[buf][mi], abase[mi] ^ xk[ks]);
#pragma unroll
                for (int nj = 0; nj < 4; nj++)
                    ldm_x4(bf[buf][nj], bbase[nj] ^ xk[ks]);
            };

            // MMA-critical LDSM first, then the prefetch burst
            load_frags(0, 0);
            if (c + 2 < KCHUNKS) issue(c + 2, s_pre);
            asm volatile("cp.async.commit_group;" ::: "memory");

#pragma unroll
            for (int ks = 0; ks < 4; ks++) {
                const int cur = ks & 1, nxt = cur ^ 1;
                if (ks < 3) load_frags(ks + 1, nxt);
#pragma unroll
                for (int mi = 0; mi < 4; mi++)
#pragma unroll
                    for (int nj = 0; nj < 4; nj++) {
                        mma16816(C[mi][2 * nj + 0], af[cur][mi],
                                 bf[cur][nj][0], bf[cur][nj][2]);
                        mma16816(C[mi][2 * nj + 1], af[cur][mi],
                                 bf[cur][nj][1], bf[cur][nj][3]);
                    }
            }
            s_cur = (s_cur == NST - 1) ? 0 : s_cur + 1;
            s_pre = (s_pre == NST - 1) ? 0 : s_pre + 1;
        }

        // epilogue: rows row0+warp_m*64+mi*16+{g, g+8},
        // cols col0+warp_n*64+nf*8+q*2 (+1)
        const int rbase = row0 + warp_m * 64 + g;
        const int cbase = col0 + warp_n * 64 + q * 2;
        float2 bv[8];
#pragma unroll
        for (int nf = 0; nf < 8; nf++) {
            bv[nf].x = __ldg(bias + cbase + nf * 8);
            bv[nf].y = __ldg(bias + cbase + nf * 8 + 1);
        }
#pragma unroll
        for (int mi = 0; mi < 4; mi++) {
            const int r_lo = rbase + mi * 16;
#pragma unroll
            for (int nf = 0; nf < 8; nf++) {
                const int cc = cbase + nf * 8;
                float2 v0, v1;
                v0.x = C[mi][nf][0] + bv[nf].x;
                v0.y = C[mi][nf][1] + bv[nf].y;
                v1.x = C[mi][nf][2] + bv[nf].x;
                v1.y = C[mi][nf][3] + bv[nf].y;
                *reinterpret_cast<float2*>(out + (size_t)r_lo * OUT_F + cc) = v0;
                *reinterpret_cast<float2*>(out + (size_t)(r_lo + 8) * OUT_F + cc) = v1;
            }
        }
        // next tile's issue() is gated by the ticket __syncthreads above
    }
}

// ---------------------------------------------------------------------------
// launch
// ---------------------------------------------------------------------------
extern "C" void kernel_launch(void* const* d_in, const int* in_sizes, int n_in,
                              void* d_out, int out_size) {
    const float* x      = (const float*)d_in[0];
    const int*   packed = (const int*)d_in[1];
    const float* absmax = (const float*)d_in[2];
    const float* bias   = (const float*)d_in[3];
    float* out = (float*)d_out;

    prep_kernel<<<CVT_BLOCKS + DEQ_BLOCKS, 256>>>(x, packed, absmax);

    cudaFuncSetAttribute(gemm_kernel,
                         cudaFuncAttributeMaxDynamicSharedMemorySize, SMEM_BYTES);
    gemm_kernel<<<GRID_PERSIST, 128, SMEM_BYTES>>>(bias, out);
}

// round 13
// speedup vs baseline: 1.0124x; 1.0124x over previous
#include <cuda_runtime.h>
#include <cuda_fp16.h>
#include <cstdint>

// Problem dims
#define IN_F   4096
#define OUT_F  11008
#define MROWS  2048
#define NUMEL  (IN_F * OUT_F)        // 45,088,768
#define PACKED_N (NUMEL / 2)         // 22,544,384

// GEMM tiling: 128x128 CTA tile, 4 warps (2x2), warp tile 64x64, 2 CTAs/SM
#define BM 128
#define BN 128
#define BK 64
#define KCHUNKS (IN_F / BK)          // 64
#define NST 3
#define A_BYTES (BM * 128)           // 16384
#define B_BYTES (BN * 128)           // 16384
#define STAGE_BYTES (A_BYTES + B_BYTES)   // 32768
#define SMEM_BYTES (NST * STAGE_BYTES + 1024)  // 99328 (x2 CTAs = 198656)

// prep kernel split
#define CVT_BLOCKS ((MROWS * IN_F / 4) / 256)   // 8192
#define DEQ_BLOCKS ((PACKED_N / 4) / 256)       // 22016

// Scratch (device globals; no allocation allowed)
__device__ __half g_W[NUMEL];          // dequantized W, row-major [OUT_F][IN_F]
__device__ __half g_X[MROWS * IN_F];   // fp16 x

__constant__ float c_nf4[16] = {
    -1.0f, -0.6961928009986877f, -0.5250730514526367f, -0.39491748809814453f,
    -0.28444138169288635f, -0.18477343022823334f, -0.09105003625154495f, 0.0f,
    0.07958029955625534f, 0.16093020141124725f, 0.24611230194568634f,
    0.33791524171829224f, 0.44070982933044434f, 0.5626170039176941f,
    0.7229568362236023f, 1.0f};

// ---------------------------------------------------------------------------
// fused prep: blocks [0, CVT_BLOCKS) convert x fp32->fp16,
//             blocks [CVT_BLOCKS, ...) dequant NF4 -> fp16 W via
//             32x-replicated conflict-free smem LUT (~35us, near DRAM floor)
// ---------------------------------------------------------------------------
__global__ void prep_kernel(const float* __restrict__ x,
                            const int* __restrict__ packed,
                            const float* __restrict__ absmax) {
    __shared__ float lut[16 * 32];
    const int b = blockIdx.x;
    const int tid = threadIdx.x;
    if (b < CVT_BLOCKS) {
        int i = b * 256 + tid;                            // handles 4 floats
        float4 v = reinterpret_cast<const float4*>(x)[i];
        __half2* o = reinterpret_cast<__half2*>(g_X);
        o[2 * i]     = __floats2half2_rn(v.x, v.y);
        o[2 * i + 1] = __floats2half2_rn(v.z, v.w);
    } else {
        lut[tid]       = c_nf4[tid >> 5];                 // uniform index
        lut[tid + 256] = c_nf4[(tid + 256) >> 5];
        __syncthreads();
        const int lane = tid & 31;
        int i = (b - CVT_BLOCKS) * 256 + tid;             // packed[4i..4i+3]
        int4 pk = reinterpret_cast<const int4*>(packed)[i];
        float s = absmax[i >> 3];                          // (4i)/32 == i/8
        int v[4] = {pk.x, pk.y, pk.z, pk.w};
        __half h[8];
#pragma unroll
        for (int j = 0; j < 4; j++) {
            float whi = lut[((v[j] >> 4) & 0xF) * 32 + lane];
            float wlo = lut[(v[j] & 0xF) * 32 + lane];
            h[2 * j]     = __float2half_rn(whi * s);
            h[2 * j + 1] = __float2half_rn(wlo * s);
        }
        reinterpret_cast<uint4*>(g_W)[i] = *reinterpret_cast<uint4*>(h);
    }
}

// ---------------------------------------------------------------------------
// PTX helpers
// ---------------------------------------------------------------------------
__device__ __forceinline__ uint32_t smem_u32(const void* p) {
    uint32_t a;
    asm("{ .reg .u64 t; cvta.to.shared.u64 t, %1; cvt.u32.u64 %0, t; }"
        : "=r"(a) : "l"(p));
    return a;
}

__device__ __forceinline__ void cp16(uint32_t saddr, const void* gaddr) {
    asm volatile("cp.async.cg.shared.global [%0], [%1], 16;"
                 :: "r"(saddr), "l"(gaddr));
}

__device__ __forceinline__ void ldm_x4(uint32_t* r, uint32_t addr) {
    asm volatile("ldmatrix.sync.aligned.m8n8.x4.shared.b16 {%0,%1,%2,%3}, [%4];"
                 : "=r"(r[0]), "=r"(r[1]), "=r"(r[2]), "=r"(r[3]) : "r"(addr));
}

__device__ __forceinline__ void mma16816(float* c, const uint32_t* a,
                                         uint32_t b0, uint32_t b1) {
    asm volatile(
        "mma.sync.aligned.m16n8k16.row.col.f32.f16.f16.f32 "
        "{%0,%1,%2,%3}, {%4,%5,%6,%7}, {%8,%9}, {%0,%1,%2,%3};"
        : "+f"(c[0]), "+f"(c[1]), "+f"(c[2]), "+f"(c[3])
        : "r"(a[0]), "r"(a[1]), "r"(a[2]), "r"(a[3]), "r"(b0), "r"(b1));
}

// ---------------------------------------------------------------------------
// GEMM: out[128,128] tile = A[128,K] * B[128,K]^T + bias, fp16 in / fp32 acc.
// Static grid (86,16) — round-12 showed persistent CTAs lose to it (per-tile
// ring drain; uniform tiles make dynamic scheduling unable to beat 5 waves).
// 128 threads = 4 warps (2x2), warp tile 64x64, double-buffered ldmatrix
// fragments, 2 CTAs/SM (independent barriers), 3-stage cp.async ring
// (distance 2), ONE __syncthreads per chunk.
// Kept from round 12: xor-folded ldsm addressing (smem base 1024-aligned ->
// bits [5:6] of folded bases are 0, so +ks*32 composes into the xor; one
// IADD fewer per LDSM — measured -6pp alu pipe) and hoisted cp.async
// per-thread constants.
// ---------------------------------------------------------------------------
__global__ void __launch_bounds__(128, 2)
gemm_kernel(const float* __restrict__ bias, float* __restrict__ out) {
    extern __shared__ char smem_raw[];
    const uint32_t sb = (smem_u32(smem_raw) + 1023u) & ~1023u;
    const int tid = threadIdx.x;
    const int wid = tid >> 5;
    const int lane = tid & 31;
    const int warp_m = wid >> 1;          // 0..1
    const int warp_n = wid & 1;           // 0..1
    const int row0 = blockIdx.y * BM;
    const int col0 = blockIdx.x * BN;

    const __half* Ab = g_X + (size_t)row0 * IN_F;
    const __half* Bb = g_W + (size_t)col0 * IN_F;

    // per-thread ldmatrix lane addressing (SW128; validated round 2)
    const int grp = lane >> 3, lr = lane & 7;
    const uint32_t xorv = (uint32_t)(lr << 4);
    uint32_t xk[4];
#pragma unroll
    for (int ks = 0; ks < 4; ks++) xk[ks] = xorv ^ (uint32_t)(ks << 5);
    const uint32_t laneoff =
        (uint32_t)((((grp & 1) << 3) + lr) << 7) + (uint32_t)((grp >> 1) << 4);
    const uint32_t aoff0 = (uint32_t)((warp_m * 64) << 7) + laneoff;
    const uint32_t boff0 = (uint32_t)((warp_n * 64) << 7) + laneoff;

    // cp.async issue constants (per-thread): 8 units x (A,B)
    uint32_t sw_i[8];
    int r_i[8], sg_i[8];
#pragma unroll
    for (int i = 0; i < 8; i++) {
        int u = tid + (i << 7);
        r_i[i] = u >> 3;
        sg_i[i] = (u & 7) * 8;
        uint32_t bo = (uint32_t)((r_i[i] << 7) + ((u & 7) << 4));
        sw_i[i] = bo ^ ((bo >> 3) & 0x70);
    }

    auto issue = [&](int c, int s) {
        const int kc = c * BK;
        const uint32_t base = sb + s * STAGE_BYTES;
#pragma unroll
        for (int i = 0; i < 8; i++) {
            cp16(base + sw_i[i], Ab + (size_t)r_i[i] * IN_F + kc + sg_i[i]);
            cp16(base + A_BYTES + sw_i[i],
                 Bb + (size_t)r_i[i] * IN_F + kc + sg_i[i]);
        }
    };

    float C[4][8][4];
#pragma unroll
    for (int a = 0; a < 4; a++)
#pragma unroll
        for (int b = 0; b < 8; b++)
#pragma unroll
            for (int d = 0; d < 4; d++) C[a][b][d] = 0.0f;

    uint32_t af[2][4][4], bf[2][4][4];

    // prologue: 2 chunks in flight
    issue(0, 0);
    asm volatile("cp.async.commit_group;" ::: "memory");
    issue(1, 1);
    asm volatile("cp.async.commit_group;" ::: "memory");

    int s_cur = 0, s_pre = 2;
#pragma unroll 1
    for (int c = 0; c < KCHUNKS; c++) {
        asm volatile("cp.async.wait_group 1;" ::: "memory");
        __syncthreads();   // chunk c landed; all warps past iter c-1 LDSM

        const uint32_t sa = sb + s_cur * STAGE_BYTES;
        const uint32_t sB = sa + A_BYTES;
        // folded ldsm bases (bits [5:6] provably 0 -> xor-composable)
        uint32_t abase[4], bbase[4];
#pragma unroll
        for (int mi = 0; mi < 4; mi++) {
            abase[mi] = sa + aoff0 + (uint32_t)(mi << 11);
            bbase[mi] = sB + boff0 + (uint32_t)(mi << 11);
        }
        auto load_frags = [&](int ks, int buf) {
#pragma unroll
            for (int mi = 0; mi < 4; mi++)
                ldm_x4(af[buf][mi], abase[mi] ^ xk[ks]);
#pragma unroll
            for (int nj = 0; nj < 4; nj++)
                ldm_x4(bf[buf][nj], bbase[nj] ^ xk[ks]);
        };

        // MMA-critical LDSM first, then the prefetch burst
        load_frags(0, 0);
        if (c + 2 < KCHUNKS) issue(c + 2, s_pre);
        asm volatile("cp.async.commit_group;" ::: "memory");

#pragma unroll
        for (int ks = 0; ks < 4; ks++) {
            const int cur = ks & 1, nxt = cur ^ 1;
            if (ks < 3) load_frags(ks + 1, nxt);
#pragma unroll
            for (int mi = 0; mi < 4; mi++)
#pragma unroll
                for (int nj = 0; nj < 4; nj++) {
                    mma16816(C[mi][2 * nj + 0], af[cur][mi],
                             bf[cur][nj][0], bf[cur][nj][2]);
                    mma16816(C[mi][2 * nj + 1], af[cur][mi],
                             bf[cur][nj][1], bf[cur][nj][3]);
                }
        }
        s_cur = (s_cur == NST - 1) ? 0 : s_cur + 1;
        s_pre = (s_pre == NST - 1) ? 0 : s_pre + 1;
        // no trailing sync: next iteration's top sync precedes stage reuse
    }

    // epilogue: rows row0+warp_m*64+mi*16+{g, g+8},
    // cols col0+warp_n*64+nf*8+q*2 (+1)
    const int g = lane >> 2, q = lane & 3;
    const int rbase = row0 + warp_m * 64 + g;
    const int cbase = col0 + warp_n * 64 + q * 2;
    float2 bv[8];
#pragma unroll
    for (int nf = 0; nf < 8; nf++) {
        bv[nf].x = __ldg(bias + cbase + nf * 8);
        bv[nf].y = __ldg(bias + cbase + nf * 8 + 1);
    }
#pragma unroll
    for (int mi = 0; mi < 4; mi++) {
        const int r_lo = rbase + mi * 16;
#pragma unroll
        for (int nf = 0; nf < 8; nf++) {
            const int cc = cbase + nf * 8;
            float2 v0, v1;
            v0.x = C[mi][nf][0] + bv[nf].x;
            v0.y = C[mi][nf][1] + bv[nf].y;
            v1.x = C[mi][nf][2] + bv[nf].x;
            v1.y = C[mi][nf][3] + bv[nf].y;
            *reinterpret_cast<float2*>(out + (size_t)r_lo * OUT_F + cc) = v0;
            *reinterpret_cast<float2*>(out + (size_t)(r_lo + 8) * OUT_F + cc) = v1;
        }
    }
}

// ---------------------------------------------------------------------------
// launch
// ---------------------------------------------------------------------------
extern "C" void kernel_launch(void* const* d_in, const int* in_sizes, int n_in,
                              void* d_out, int out_size) {
    const float* x      = (const float*)d_in[0];
    const int*   packed = (const int*)d_in[1];
    const float* absmax = (const float*)d_in[2];
    const float* bias   = (const float*)d_in[3];
    float* out = (float*)d_out;

    prep_kernel<<<CVT_BLOCKS + DEQ_BLOCKS, 256>>>(x, packed, absmax);

    cudaFuncSetAttribute(gemm_kernel,
                         cudaFuncAttributeMaxDynamicSharedMemorySize, SMEM_BYTES);
    dim3 grid(OUT_F / BN, MROWS / BM);  // (86, 16)
    gemm_kernel<<<grid, 128, SMEM_BYTES>>>(bias, out);
}

// round 14
// speedup vs baseline: 1.0504x; 1.0375x over previous
#include <cuda_runtime.h>
#include <cuda_fp16.h>
#include <cstdint>

// Problem dims
#define IN_F   4096
#define OUT_F  11008
#define MROWS  2048
#define NUMEL  (IN_F * OUT_F)        // 45,088,768
#define PACKED_N (NUMEL / 2)         // 22,544,384

// GEMM tiling: 128x128 CTA tile, 4 warps (2x2), warp tile 64x64, 2 CTAs/SM
#define BM 128
#define BN 128
#define BK 64
#define KCHUNKS (IN_F / BK)          // 64
#define NST 3
#define A_BYTES (BM * 128)           // 16384
#define B_BYTES (BN * 128)           // 16384
#define STAGE_BYTES (A_BYTES + B_BYTES)   // 32768
#define SMEM_BYTES (NST * STAGE_BYTES)    // 98304 (x2 CTAs = 196608 <= 228KB)

// prep kernel split
#define CVT_BLOCKS ((MROWS * IN_F / 4) / 256)   // 8192
#define DEQ_BLOCKS ((PACKED_N / 4) / 256)       // 22016

// Scratch (device globals; no allocation allowed)
__device__ __half g_W[NUMEL];          // dequantized W, row-major [OUT_F][IN_F]
__device__ __half g_X[MROWS * IN_F];   // fp16 x

__constant__ float c_nf4[16] = {
    -1.0f, -0.6961928009986877f, -0.5250730514526367f, -0.39491748809814453f,
    -0.28444138169288635f, -0.18477343022823334f, -0.09105003625154495f, 0.0f,
    0.07958029955625534f, 0.16093020141124725f, 0.24611230194568634f,
    0.33791524171829224f, 0.44070982933044434f, 0.5626170039176941f,
    0.7229568362236023f, 1.0f};

// ---------------------------------------------------------------------------
// fused prep: blocks [0, CVT_BLOCKS) convert x fp32->fp16,
//             blocks [CVT_BLOCKS, ...) dequant NF4 -> fp16 W via
//             32x-replicated conflict-free smem LUT (~35us, near DRAM floor)
// ---------------------------------------------------------------------------
__global__ void prep_kernel(const float* __restrict__ x,
                            const int* __restrict__ packed,
                            const float* __restrict__ absmax) {
    __shared__ float lut[16 * 32];
    const int b = blockIdx.x;
    const int tid = threadIdx.x;
    if (b < CVT_BLOCKS) {
        int i = b * 256 + tid;                            // handles 4 floats
        float4 v = reinterpret_cast<const float4*>(x)[i];
        __half2* o = reinterpret_cast<__half2*>(g_X);
        o[2 * i]     = __floats2half2_rn(v.x, v.y);
        o[2 * i + 1] = __floats2half2_rn(v.z, v.w);
    } else {
        lut[tid]       = c_nf4[tid >> 5];                 // uniform index
        lut[tid + 256] = c_nf4[(tid + 256) >> 5];
        __syncthreads();
        const int lane = tid & 31;
        int i = (b - CVT_BLOCKS) * 256 + tid;             // packed[4i..4i+3]
        int4 pk = reinterpret_cast<const int4*>(packed)[i];
        float s = absmax[i >> 3];                          // (4i)/32 == i/8
        int v[4] = {pk.x, pk.y, pk.z, pk.w};
        __half h[8];
#pragma unroll
        for (int j = 0; j < 4; j++) {
            float whi = lut[((v[j] >> 4) & 0xF) * 32 + lane];
            float wlo = lut[(v[j] & 0xF) * 32 + lane];
            h[2 * j]     = __float2half_rn(whi * s);
            h[2 * j + 1] = __float2half_rn(wlo * s);
        }
        reinterpret_cast<uint4*>(g_W)[i] = *reinterpret_cast<uint4*>(h);
    }
}

// ---------------------------------------------------------------------------
// PTX helpers
// ---------------------------------------------------------------------------
__device__ __forceinline__ uint32_t smem_u32(const void* p) {
    uint32_t a;
    asm("{ .reg .u64 t; cvta.to.shared.u64 t, %1; cvt.u32.u64 %0, t; }"
        : "=r"(a) : "l"(p));
    return a;
}

__device__ __forceinline__ void cp16(uint32_t saddr, const void* gaddr) {
    asm volatile("cp.async.cg.shared.global [%0], [%1], 16;"
                 :: "r"(saddr), "l"(gaddr));
}

__device__ __forceinline__ void ldm_x4(uint32_t* r, uint32_t addr) {
    asm volatile("ldmatrix.sync.aligned.m8n8.x4.shared.b16 {%0,%1,%2,%3}, [%4];"
                 : "=r"(r[0]), "=r"(r[1]), "=r"(r[2]), "=r"(r[3]) : "r"(addr));
}

__device__ __forceinline__ void mma16816(float* c, const uint32_t* a,
                                         uint32_t b0, uint32_t b1) {
    asm volatile(
        "mma.sync.aligned.m16n8k16.row.col.f32.f16.f16.f32 "
        "{%0,%1,%2,%3}, {%4,%5,%6,%7}, {%8,%9}, {%0,%1,%2,%3};"
        : "+f"(c[0]), "+f"(c[1]), "+f"(c[2]), "+f"(c[3])
        : "r"(a[0]), "r"(a[1]), "r"(a[2]), "r"(a[3]), "r"(b0), "r"(b1));
}

__device__ __forceinline__ void stg_cs_v2(float* p, float vx, float vy) {
    asm volatile("st.global.cs.v2.f32 [%0], {%1, %2};"
                 :: "l"(p), "f"(vx), "f"(vy) : "memory");
}

// ---------------------------------------------------------------------------
// GEMM: out[128,128] tile = A[128,K] * B[128,K]^T + bias, fp16 in / fp32 acc.
// Exact round-11 structure (best: gemm 514.9us, 242 regs): 128 threads =
// 4 warps (2x2), warp tile 64x64, double-buffered ldmatrix fragments,
// 2 CTAs/SM (independent barriers cover each other's bubbles), 3-stage
// cp.async ring (distance 2), ONE __syncthreads per chunk, stage index via
// wrap counter. NO hoisted constant arrays (round 13: they push 242->254
// regs and regress). Round-14 change: epilogue stores use st.global.cs
// (streaming; output is write-once, keep it from evicting reused A/B in L2).
// ---------------------------------------------------------------------------
__global__ void __launch_bounds__(128, 2)
gemm_kernel(const float* __restrict__ bias, float* __restrict__ out) {
    extern __shared__ char smem[];
    const uint32_t sb = smem_u32(smem);
    const int tid = threadIdx.x;
    const int wid = tid >> 5;
    const int lane = tid & 31;
    const int warp_m = wid >> 1;          // 0..1
    const int warp_n = wid & 1;           // 0..1
    const int row0 = blockIdx.y * BM;
    const int col0 = blockIdx.x * BN;

    const __half* Ab = g_X + (size_t)row0 * IN_F;
    const __half* Bb = g_W + (size_t)col0 * IN_F;

    // cp.async of chunk c into stage s (128 thr: 8 A + 8 B units each)
    auto issue = [&](int c, int s) {
        const int kc = c * BK;
        const uint32_t base = sb + s * STAGE_BYTES;
#pragma unroll
        for (int i = 0; i < 8; i++) {     // 1024 16B units per tile / 128 thr
            int u = tid + (i << 7);
            int r = u >> 3, sg = u & 7;
            uint32_t bo = (uint32_t)((r << 7) + (sg << 4));
            uint32_t sw = bo ^ ((bo >> 3) & 0x70);
            cp16(base + sw, Ab + (size_t)r * IN_F + kc + sg * 8);
            cp16(base + A_BYTES + sw, Bb + (size_t)r * IN_F + kc + sg * 8);
        }
    };

    // per-thread ldmatrix lane addressing (SW128; validated round 2)
    const int grp = lane >> 3, lr = lane & 7;
    const uint32_t xorv = (uint32_t)(lr << 4);
    const uint32_t laneoff =
        (uint32_t)((((grp & 1) << 3) + lr) << 7) + (uint32_t)((grp >> 1) << 4);
    const uint32_t aoff0 = (uint32_t)((warp_m * 64) << 7) + laneoff;
    const uint32_t boff0 = (uint32_t)((warp_n * 64) << 7) + laneoff;

    float C[4][8][4];
#pragma unroll
    for (int a = 0; a < 4; a++)
#pragma unroll
        for (int b = 0; b < 8; b++)
#pragma unroll
            for (int d = 0; d < 4; d++) C[a][b][d] = 0.0f;

    // double-buffered fragments
    uint32_t af[2][4][4], bf[2][4][4];
    auto load_frags = [&](uint32_t sa, uint32_t sB, int ks, int buf) {
#pragma unroll
        for (int mi = 0; mi < 4; mi++)
            ldm_x4(af[buf][mi], (sa + aoff0 + (uint32_t)(mi << 11) +
                                 (uint32_t)(ks << 5)) ^ xorv);
#pragma unroll
        for (int nj = 0; nj < 4; nj++)
            ldm_x4(bf[buf][nj], (sB + boff0 + (uint32_t)(nj << 11) +
                                 (uint32_t)(ks << 5)) ^ xorv);
    };

    // prologue: 2 chunks in flight
    issue(0, 0);
    asm volatile("cp.async.commit_group;" ::: "memory");
    issue(1, 1);
    asm volatile("cp.async.commit_group;" ::: "memory");

    int s_cur = 0;     // stage of chunk c
    int s_pre = 2;     // stage for chunk c+2
#pragma unroll 1
    for (int c = 0; c < KCHUNKS; c++) {
        asm volatile("cp.async.wait_group 1;" ::: "memory");
        __syncthreads();   // chunk c landed; all warps done with iter c-1 LDSM

        const uint32_t sa = sb + s_cur * STAGE_BYTES;
        const uint32_t sB = sa + A_BYTES;

        // MMA-critical LDSM first, then the prefetch burst
        load_frags(sa, sB, 0, 0);
        if (c + 2 < KCHUNKS) issue(c + 2, s_pre);
        asm volatile("cp.async.commit_group;" ::: "memory");

#pragma unroll
        for (int ks = 0; ks < 4; ks++) {
            const int cur = ks & 1, nxt = cur ^ 1;
            if (ks < 3) load_frags(sa, sB, ks + 1, nxt);
#pragma unroll
            for (int mi = 0; mi < 4; mi++)
#pragma unroll
                for (int nj = 0; nj < 4; nj++) {
                    mma16816(C[mi][2 * nj + 0], af[cur][mi],
                             bf[cur][nj][0], bf[cur][nj][2]);
                    mma16816(C[mi][2 * nj + 1], af[cur][mi],
                             bf[cur][nj][1], bf[cur][nj][3]);
                }
        }
        // stage counters: wrap without %
        s_cur = (s_cur == NST - 1) ? 0 : s_cur + 1;
        s_pre = (s_pre == NST - 1) ? 0 : s_pre + 1;
        // no trailing sync: next iteration's top sync precedes stage reuse
    }

    // epilogue: D frag (mi, nf): rows row0+warp_m*64+mi*16+{g, g+8},
    // cols col0+warp_n*64+nf*8+q*2 (+1); streaming stores
    const int g = lane >> 2, q = lane & 3;
    const int rbase = row0 + warp_m * 64 + g;
    const int cbase = col0 + warp_n * 64 + q * 2;
    float2 bv[8];
#pragma unroll
    for (int nf = 0; nf < 8; nf++) {
        bv[nf].x = __ldg(bias + cbase + nf * 8);
        bv[nf].y = __ldg(bias + cbase + nf * 8 + 1);
    }
#pragma unroll
    for (int mi = 0; mi < 4; mi++) {
        const int r_lo = rbase + mi * 16;
#pragma unroll
        for (int nf = 0; nf < 8; nf++) {
            const int cc = cbase + nf * 8;
            stg_cs_v2(out + (size_t)r_lo * OUT_F + cc,
                      C[mi][nf][0] + bv[nf].x, C[mi][nf][1] + bv[nf].y);
            stg_cs_v2(out + (size_t)(r_lo + 8) * OUT_F + cc,
                      C[mi][nf][2] + bv[nf].x, C[mi][nf][3] + bv[nf].y);
        }
    }
}

// ---------------------------------------------------------------------------
// launch
// ---------------------------------------------------------------------------
extern "C" void kernel_launch(void* const* d_in, const int* in_sizes, int n_in,
                              void* d_out, int out_size) {
    const float* x      = (const float*)d_in[0];
    const int*   packed = (const int*)d_in[1];
    const float* absmax = (const float*)d_in[2];
    const float* bias   = (const float*)d_in[3];
    float* out = (float*)d_out;

    prep_kernel<<<CVT_BLOCKS + DEQ_BLOCKS, 256>>>(x, packed, absmax);

    cudaFuncSetAttribute(gemm_kernel,
                         cudaFuncAttributeMaxDynamicSharedMemorySize, SMEM_BYTES);
    dim3 grid(OUT_F / BN, MROWS / BM);  // (86, 16)
    gemm_kernel<<<grid, 128, SMEM_BYTES>>>(bias, out);
}